// round 15
// baseline (speedup 1.0000x reference)
#include <cuda_runtime.h>
#include <cuda_fp16.h>
#include <cstdint>

// Problem constants (fixed by the dataset)
constexpr int D      = 128;     // embed size
constexpr int H      = 256;     // hidden size
constexpr int NODES  = 8192;    // 2*B
constexpr int BP     = 4096;    // pairs
constexpr int T_EDG  = NODES * 32;
constexpr int K1     = 3 * D;   // 384
constexpr int K2     = 2 * H;   // 512

// Scratch
__device__ __half g_A1[(size_t)NODES * K1];   // fp16 gather output
__device__ __half g_W1p[K1 * H];              // W1 packed in mma-fragment order
__device__ __half g_Wrp[K2 * H];              // Wr packed in mma-fragment order
__device__ float  g_b1[H];

// ---------------------------------------------------------------------------
// Kernel 1: gather + segment mean, TWO warps per node. MONOLITHIC.
// Fused: fp16 m16n8k16 weight-fragment packing + bias fuse (free rider).
// Packed word w (half2): r=w&1, lane=(w>>1)&31, j=(w>>6)&31, t=w>>11.
//   k  = t*16 + (lane&3)*2 + r*8   (pair k, k+1)
//   col= j*8 + (lane>>2)
// ---------------------------------------------------------------------------
__global__ void gather_mean(const float* __restrict__ E, const float* __restrict__ R,
                            const int* __restrict__ ents,
                            const int* __restrict__ nent,
                            const int* __restrict__ nrel,
                            const int* __restrict__ offs,
                            const float* __restrict__ Wt,
                            const float* __restrict__ Wn,
                            const float* __restrict__ Wr,
                            const float* __restrict__ bt,
                            const float* __restrict__ bn) {
    // ---- fused weight pack (independent of gather work) ----
    {
        const int w = blockIdx.x * blockDim.x + threadIdx.x;
        const int W1W = K1 * H / 2;   // 49152 half2 words
        const int WRW = K2 * H / 2;   // 65536
        if (w < W1W) {
            const int r = w & 1, lane = (w >> 1) & 31, j = (w >> 6) & 31, t = w >> 11;
            const int gk  = t * 16 + (lane & 3) * 2 + r * 8;
            const int col = j * 8 + (lane >> 2);
            const float f0 = (gk     < D) ? Wt[gk * H + col]       : Wn[(gk - D) * H + col];
            const float f1 = (gk + 1 < D) ? Wt[(gk + 1) * H + col] : Wn[(gk + 1 - D) * H + col];
            ((half2*)g_W1p)[w] = __floats2half2_rn(f0, f1);
        } else if (w < W1W + WRW) {
            const int idx = w - W1W;
            const int r = idx & 1, lane = (idx >> 1) & 31, j = (idx >> 6) & 31, t = idx >> 11;
            const int gk  = t * 16 + (lane & 3) * 2 + r * 8;
            const int col = j * 8 + (lane >> 2);
            ((half2*)g_Wrp)[idx] =
                __floats2half2_rn(Wr[gk * H + col], Wr[(gk + 1) * H + col]);
        }
        if (w < H) g_b1[w] = bt[w] + bn[w];
    }

    const int gw   = (blockIdx.x * blockDim.x + threadIdx.x) >> 5;
    const int lane = threadIdx.x & 31;
    const int node = gw >> 1;
    const bool isE = (gw & 1) == 0;
    if (node >= NODES) return;

    const int start = offs[node];
    const int end   = (node + 1 < NODES) ? offs[node + 1] : T_EDG;
    const int cnt   = end - start;
    const float inv = 1.0f / (float)(cnt > 0 ? cnt : 1);

    __half* row = g_A1 + (size_t)node * K1;

    if (isE) {
        const float4* E4 = (const float4*)E;
        float4 s = make_float4(0.f, 0.f, 0.f, 0.f);
        if (cnt == 32) {
            const int idx = nent[start + lane];
            #pragma unroll 16
            for (int j = 0; j < 32; j++) {
                const int ie = __shfl_sync(0xffffffffu, idx, j);
                float4 v = __ldg(&E4[(size_t)ie * (D / 4) + lane]);
                s.x += v.x; s.y += v.y; s.z += v.z; s.w += v.w;
            }
        } else {
            for (int base = start; base < end; base += 32) {
                const int rem = end - base;
                const int n   = rem < 32 ? rem : 32;
                const int idx = (lane < rem) ? nent[base + lane] : 0;
                #pragma unroll 4
                for (int j = 0; j < n; j++) {
                    const int ie = __shfl_sync(0xffffffffu, idx, j);
                    float4 v = __ldg(&E4[(size_t)ie * (D / 4) + lane]);
                    s.x += v.x; s.y += v.y; s.z += v.z; s.w += v.w;
                }
            }
        }
        float4 e = __ldg(&E4[(size_t)ents[node] * (D / 4) + lane]);
        *(half2*)(row + lane * 4)         = __floats2half2_rn(e.x, e.y);
        *(half2*)(row + lane * 4 + 2)     = __floats2half2_rn(e.z, e.w);
        *(half2*)(row + D + lane * 4)     = __floats2half2_rn(s.x * inv, s.y * inv);
        *(half2*)(row + D + lane * 4 + 2) = __floats2half2_rn(s.z * inv, s.w * inv);
    } else {
        const float4* R4 = (const float4*)R;
        float4 s = make_float4(0.f, 0.f, 0.f, 0.f);
        if (cnt == 32) {
            const int idx = nrel[start + lane];
            #pragma unroll 16
            for (int j = 0; j < 32; j++) {
                const int ir = __shfl_sync(0xffffffffu, idx, j);
                float4 v = __ldg(&R4[(size_t)ir * (D / 4) + lane]);
                s.x += v.x; s.y += v.y; s.z += v.z; s.w += v.w;
            }
        } else {
            for (int base = start; base < end; base += 32) {
                const int rem = end - base;
                const int n   = rem < 32 ? rem : 32;
                const int idx = (lane < rem) ? nrel[base + lane] : 0;
                #pragma unroll 4
                for (int j = 0; j < n; j++) {
                    const int ir = __shfl_sync(0xffffffffu, idx, j);
                    float4 v = __ldg(&R4[(size_t)ir * (D / 4) + lane]);
                    s.x += v.x; s.y += v.y; s.z += v.z; s.w += v.w;
                }
            }
        }
        *(half2*)(row + 2 * D + lane * 4)     = __floats2half2_rn(s.x * inv, s.y * inv);
        *(half2*)(row + 2 * D + lane * 4 + 2) = __floats2half2_rn(s.z * inv, s.w * inv);
    }
}

// ---------------------------------------------------------------------------
__device__ __forceinline__ void cp16(void* smem, const void* gmem) {
    uint32_t s = (uint32_t)__cvta_generic_to_shared(smem);
    asm volatile("cp.async.cg.shared.global [%0], [%1], 16;" :: "r"(s), "l"(gmem));
}
__device__ __forceinline__ void mma_f16(float* a4, uint32_t a0, uint32_t a1,
                                        uint32_t a2, uint32_t a3,
                                        uint32_t b0, uint32_t b1) {
    asm volatile(
        "mma.sync.aligned.m16n8k16.row.col.f32.f16.f16.f32 "
        "{%0,%1,%2,%3}, {%4,%5,%6,%7}, {%8,%9}, {%0,%1,%2,%3};"
        : "+f"(a4[0]), "+f"(a4[1]), "+f"(a4[2]), "+f"(a4[3])
        : "r"(a0), "r"(a1), "r"(a2), "r"(a3), "r"(b0), "r"(b1));
}

// ---------------------------------------------------------------------------
// Fused MLP (fp16, BK=32, 512 threads = 16 warps, 2 CTAs/SM):
//   one CTA per 32 node-rows (= 16 pairs), 256 CTAs.
// Phase 1 (12 iters): warps 2x8, warp tile 16x32 -> nodeTile[32,256] in sN
// Phase 2 (16 iters): warps 1x16, warp tile 16x16 -> out[16,256]
// ---------------------------------------------------------------------------
constexpr int BKH    = 32;                 // k per pipeline tile (2 x k16 mma)
constexpr int STAGES = 3;
constexpr int BM     = 32;
constexpr int SAS2   = 40;                 // A-tile halfs/row (32 data + 8 pad)
constexpr int SN2    = 260;                // sN halfs per row
constexpr int A_SZH  = BM * SAS2;          // 1280 halfs / stage
constexpr int B_SZH  = BKH * H;            // 8192 halfs / stage
constexpr int SN_H   = BM * SN2;           // 8320 halfs
constexpr int FUSED_SMEM =
    (SN_H + STAGES * A_SZH + STAGES * B_SZH) * 2;    // 73472 B

__global__ void __launch_bounds__(512, 2)
fused_mlp(const __half* __restrict__ A1full, const __half* __restrict__ W1p,
          const float* __restrict__ b1g, const __half* __restrict__ Wrp,
          const float* __restrict__ br, float* __restrict__ out) {
    constexpr int THREADS = 512;

    extern __shared__ __align__(16) __half smh[];
    __half* sN  = smh;                       // [32][SN2]
    __half* sAb = smh + SN_H;                // STAGES * A_SZH
    __half* sBb = sAb + STAGES * A_SZH;      // STAGES * B_SZH

    const int tid  = threadIdx.x;
    const int wid  = tid >> 5;
    const int lane = tid & 31;
    const int grp  = lane >> 2;
    const int tg   = lane & 3;
    const int by   = blockIdx.x;

    const __half* Ag = A1full + (size_t)by * BM * K1;

    auto issueA = [&](int t, int stg) {
        // 32 rows * 4 chunks(16B = 8 halfs) = 128; threads 0..127
        if (tid < 128) {
            __half* sA = sAb + stg * A_SZH;
            int row = tid >> 2;
            int c4  = tid & 3;
            cp16(sA + row * SAS2 + c4 * 8,
                 Ag + (size_t)row * K1 + t * BKH + c4 * 8);
        }
    };
    auto issueB = [&](const __half* Wsrc, int t, int stg) {
        __half* sB = sBb + stg * B_SZH;
        const __half* src = Wsrc + (size_t)t * B_SZH;
        #pragma unroll
        for (int l = 0; l < 2; l++) {        // 8192 halfs / (512 thr * 8) = 2
            int o = (tid + l * THREADS) * 8;
            cp16(sB + o, src + o);
        }
    };

    // =========================== PHASE 1 ===================================
    // warps 2x8: wm = wid&1 (rows), wn = wid>>1 (cols 0..7); warp tile 16x32
    {
        const int wm = wid & 1;
        const int wn = wid >> 1;

        float acc[4][4];
        #pragma unroll
        for (int j = 0; j < 4; j++)
            #pragma unroll
            for (int c = 0; c < 4; c++) acc[j][c] = 0.f;

        const int nt1 = K1 / BKH;   // 12
        #pragma unroll
        for (int s = 0; s < STAGES - 1; s++) {
            issueA(s, s); issueB(W1p, s, s);
            asm volatile("cp.async.commit_group;");
        }

        const int rb = wm * 16 + grp;
        for (int t = 0; t < nt1; t++) {
            asm volatile("cp.async.wait_group %0;" :: "n"(STAGES - 2));
            __syncthreads();
            const int nt = t + STAGES - 1;
            if (nt < nt1) { issueA(nt, nt % STAGES); issueB(W1p, nt, nt % STAGES); }
            asm volatile("cp.async.commit_group;");

            const uint32_t* sAw = (const uint32_t*)(sAb + (t % STAGES) * A_SZH);
            const uint2*    sBq = (const uint2*)(sBb + (t % STAGES) * B_SZH);

            #pragma unroll
            for (int ks = 0; ks < 2; ks++) {
                const uint32_t a0 = sAw[(rb + 0) * (SAS2 / 2) + ks * 8 + tg];
                const uint32_t a1 = sAw[(rb + 8) * (SAS2 / 2) + ks * 8 + tg];
                const uint32_t a2 = sAw[(rb + 0) * (SAS2 / 2) + ks * 8 + 4 + tg];
                const uint32_t a3 = sAw[(rb + 8) * (SAS2 / 2) + ks * 8 + 4 + tg];
                #pragma unroll
                for (int jl = 0; jl < 4; jl++) {
                    const int j = wn * 4 + jl;
                    uint2 b = sBq[ks * 1024 + j * 32 + lane];
                    mma_f16(acc[jl], a0, a1, a2, a3, b.x, b.y);
                }
            }
        }

        asm volatile("cp.async.wait_group 0;");

        // epilogue 1: bias + relu + fp16 -> sN
        half2* sNh2 = (half2*)sN;
        #pragma unroll
        for (int jl = 0; jl < 4; jl++) {
            const int c = wn * 32 + jl * 8 + tg * 2;
            const float b0 = b1g[c], b1v = b1g[c + 1];
            sNh2[((rb + 0) * SN2 + c) >> 1] =
                __floats2half2_rn(fmaxf(acc[jl][0] + b0, 0.f),
                                  fmaxf(acc[jl][1] + b1v, 0.f));
            sNh2[((rb + 8) * SN2 + c) >> 1] =
                __floats2half2_rn(fmaxf(acc[jl][2] + b0, 0.f),
                                  fmaxf(acc[jl][3] + b1v, 0.f));
        }
        __syncthreads();
    }

    // =========================== PHASE 2 ===================================
    // 16 pairs x 256; warps 1x16 (wn2 = wid); warp tile 16x16 (NF=2)
    // A(p,k) = sN[(2p + (k>=256)) * SN2 + (k&255)]
    {
        const int wn2 = wid;
        const uint32_t* sNw = (const uint32_t*)sN;

        float acc[2][4];
        #pragma unroll
        for (int j = 0; j < 2; j++)
            #pragma unroll
            for (int c = 0; c < 4; c++) acc[j][c] = 0.f;

        const int nt2 = K2 / BKH;   // 16
        #pragma unroll
        for (int s = 0; s < STAGES - 1; s++) {
            issueB(Wrp, s, s);
            asm volatile("cp.async.commit_group;");
        }

        for (int t = 0; t < nt2; t++) {
            asm volatile("cp.async.wait_group %0;" :: "n"(STAGES - 2));
            __syncthreads();
            const int nt = t + STAGES - 1;
            if (nt < nt2) issueB(Wrp, nt, nt % STAGES);
            asm volatile("cp.async.commit_group;");

            const uint2* sBq = (const uint2*)(sBb + (t % STAGES) * B_SZH);

            #pragma unroll
            for (int ks = 0; ks < 2; ks++) {
                const int k   = t * BKH + ks * 16;
                const int h   = (k >= 256) ? 1 : 0;
                const int kk2 = (k & 255) >> 1;

                const uint32_t a0 = sNw[(2 * (grp + 0) + h) * (SN2 / 2) + kk2 + tg];
                const uint32_t a1 = sNw[(2 * (grp + 8) + h) * (SN2 / 2) + kk2 + tg];
                const uint32_t a2 = sNw[(2 * (grp + 0) + h) * (SN2 / 2) + kk2 + 4 + tg];
                const uint32_t a3 = sNw[(2 * (grp + 8) + h) * (SN2 / 2) + kk2 + 4 + tg];
                #pragma unroll
                for (int jl = 0; jl < 2; jl++) {
                    const int j = wn2 * 2 + jl;
                    uint2 b = sBq[ks * 1024 + j * 32 + lane];
                    mma_f16(acc[jl], a0, a1, a2, a3, b.x, b.y);
                }
            }
        }

        // epilogue 2: bias + relu -> gmem (fp32)
        const int prow = by * 16 + grp;
        #pragma unroll
        for (int jl = 0; jl < 2; jl++) {
            const int c = wn2 * 16 + jl * 8 + tg * 2;
            const float b0 = br[c], b1v = br[c + 1];
            float2 v0, v1;
            v0.x = fmaxf(acc[jl][0] + b0, 0.f);
            v0.y = fmaxf(acc[jl][1] + b1v, 0.f);
            v1.x = fmaxf(acc[jl][2] + b0, 0.f);
            v1.y = fmaxf(acc[jl][3] + b1v, 0.f);
            *(float2*)(out + (size_t)(prow + 0) * H + c) = v0;
            *(float2*)(out + (size_t)(prow + 8) * H + c) = v1;
        }
    }
}

// ---------------------------------------------------------------------------
extern "C" void kernel_launch(void* const* d_in, const int* in_sizes, int n_in,
                              void* d_out, int out_size) {
    const float* E    = (const float*)d_in[0];
    const float* R    = (const float*)d_in[1];
    const float* Wt   = (const float*)d_in[2];
    const float* bt   = (const float*)d_in[3];
    const float* Wn   = (const float*)d_in[4];
    const float* bn   = (const float*)d_in[5];
    const float* Wr   = (const float*)d_in[6];
    const float* br   = (const float*)d_in[7];
    const int*   ents = (const int*)d_in[8];
    const int*   nent = (const int*)d_in[9];
    const int*   nrel = (const int*)d_in[10];
    const int*   offs = (const int*)d_in[11];
    float* out = (float*)d_out;

    __half *A1, *W1p, *Wrp;
    float  *b1;
    cudaGetSymbolAddress((void**)&A1,  g_A1);
    cudaGetSymbolAddress((void**)&W1p, g_W1p);
    cudaGetSymbolAddress((void**)&Wrp, g_Wrp);
    cudaGetSymbolAddress((void**)&b1,  g_b1);

    cudaFuncSetAttribute(fused_mlp,
                         cudaFuncAttributeMaxDynamicSharedMemorySize, FUSED_SMEM);

    // 1) gather + segment mean (+ fused fp16 weight pack), MONOLITHIC
    gather_mean<<<NODES / 4, 256>>>(E, R, ents, nent, nrel, offs,
                                    Wt, Wn, Wr, bt, bn);

    // 2+3) fused node-MLP + pair-MLP (fp16, BK=32): 256 CTAs x 512 threads
    fused_mlp<<<NODES / BM, 512, FUSED_SMEM>>>(A1, W1p, b1, Wrp, br, out);
}

// round 16
// speedup vs baseline: 1.0782x; 1.0782x over previous
#include <cuda_runtime.h>
#include <cuda_fp16.h>
#include <cstdint>

// Problem constants (fixed by the dataset)
constexpr int D      = 128;     // embed size
constexpr int H      = 256;     // hidden size
constexpr int NODES  = 8192;    // 2*B
constexpr int BP     = 4096;    // pairs
constexpr int T_EDG  = NODES * 32;
constexpr int K1     = 3 * D;   // 384
constexpr int K2     = 2 * H;   // 512

// Scratch
__device__ __half g_A1[(size_t)NODES * K1];   // fp16 gather output
__device__ __half g_W1p[K1 * H];              // W1 packed in mma-fragment order
__device__ __half g_Wrp[K2 * H];              // Wr packed in mma-fragment order
__device__ float  g_b1[H];

// ---------------------------------------------------------------------------
// Kernel 1: gather + segment mean, TWO warps per node. MONOLITHIC.
// Fused: fp16 m16n8k16 weight-fragment packing + bias fuse (free rider).
// Packed word w (half2): r=w&1, lane=(w>>1)&31, j=(w>>6)&31, t=w>>11.
//   k  = t*16 + (lane&3)*2 + r*8   (pair k, k+1)
//   col= j*8 + (lane>>2)
// ---------------------------------------------------------------------------
__global__ void gather_mean(const float* __restrict__ E, const float* __restrict__ R,
                            const int* __restrict__ ents,
                            const int* __restrict__ nent,
                            const int* __restrict__ nrel,
                            const int* __restrict__ offs,
                            const float* __restrict__ Wt,
                            const float* __restrict__ Wn,
                            const float* __restrict__ Wr,
                            const float* __restrict__ bt,
                            const float* __restrict__ bn) {
    // ---- fused weight pack (independent of gather work) ----
    {
        const int w = blockIdx.x * blockDim.x + threadIdx.x;
        const int W1W = K1 * H / 2;   // 49152 half2 words
        const int WRW = K2 * H / 2;   // 65536
        if (w < W1W) {
            const int r = w & 1, lane = (w >> 1) & 31, j = (w >> 6) & 31, t = w >> 11;
            const int gk  = t * 16 + (lane & 3) * 2 + r * 8;
            const int col = j * 8 + (lane >> 2);
            const float f0 = (gk     < D) ? Wt[gk * H + col]       : Wn[(gk - D) * H + col];
            const float f1 = (gk + 1 < D) ? Wt[(gk + 1) * H + col] : Wn[(gk + 1 - D) * H + col];
            ((half2*)g_W1p)[w] = __floats2half2_rn(f0, f1);
        } else if (w < W1W + WRW) {
            const int idx = w - W1W;
            const int r = idx & 1, lane = (idx >> 1) & 31, j = (idx >> 6) & 31, t = idx >> 11;
            const int gk  = t * 16 + (lane & 3) * 2 + r * 8;
            const int col = j * 8 + (lane >> 2);
            ((half2*)g_Wrp)[idx] =
                __floats2half2_rn(Wr[gk * H + col], Wr[(gk + 1) * H + col]);
        }
        if (w < H) g_b1[w] = bt[w] + bn[w];
    }

    const int gw   = (blockIdx.x * blockDim.x + threadIdx.x) >> 5;
    const int lane = threadIdx.x & 31;
    const int node = gw >> 1;
    const bool isE = (gw & 1) == 0;
    if (node >= NODES) return;

    const int start = offs[node];
    const int end   = (node + 1 < NODES) ? offs[node + 1] : T_EDG;
    const int cnt   = end - start;
    const float inv = 1.0f / (float)(cnt > 0 ? cnt : 1);

    __half* row = g_A1 + (size_t)node * K1;

    if (isE) {
        const float4* E4 = (const float4*)E;
        float4 s = make_float4(0.f, 0.f, 0.f, 0.f);
        if (cnt == 32) {
            const int idx = nent[start + lane];
            #pragma unroll 16
            for (int j = 0; j < 32; j++) {
                const int ie = __shfl_sync(0xffffffffu, idx, j);
                float4 v = __ldg(&E4[(size_t)ie * (D / 4) + lane]);
                s.x += v.x; s.y += v.y; s.z += v.z; s.w += v.w;
            }
        } else {
            for (int base = start; base < end; base += 32) {
                const int rem = end - base;
                const int n   = rem < 32 ? rem : 32;
                const int idx = (lane < rem) ? nent[base + lane] : 0;
                #pragma unroll 4
                for (int j = 0; j < n; j++) {
                    const int ie = __shfl_sync(0xffffffffu, idx, j);
                    float4 v = __ldg(&E4[(size_t)ie * (D / 4) + lane]);
                    s.x += v.x; s.y += v.y; s.z += v.z; s.w += v.w;
                }
            }
        }
        float4 e = __ldg(&E4[(size_t)ents[node] * (D / 4) + lane]);
        *(half2*)(row + lane * 4)         = __floats2half2_rn(e.x, e.y);
        *(half2*)(row + lane * 4 + 2)     = __floats2half2_rn(e.z, e.w);
        *(half2*)(row + D + lane * 4)     = __floats2half2_rn(s.x * inv, s.y * inv);
        *(half2*)(row + D + lane * 4 + 2) = __floats2half2_rn(s.z * inv, s.w * inv);
    } else {
        const float4* R4 = (const float4*)R;
        float4 s = make_float4(0.f, 0.f, 0.f, 0.f);
        if (cnt == 32) {
            const int idx = nrel[start + lane];
            #pragma unroll 16
            for (int j = 0; j < 32; j++) {
                const int ir = __shfl_sync(0xffffffffu, idx, j);
                float4 v = __ldg(&R4[(size_t)ir * (D / 4) + lane]);
                s.x += v.x; s.y += v.y; s.z += v.z; s.w += v.w;
            }
        } else {
            for (int base = start; base < end; base += 32) {
                const int rem = end - base;
                const int n   = rem < 32 ? rem : 32;
                const int idx = (lane < rem) ? nrel[base + lane] : 0;
                #pragma unroll 4
                for (int j = 0; j < n; j++) {
                    const int ir = __shfl_sync(0xffffffffu, idx, j);
                    float4 v = __ldg(&R4[(size_t)ir * (D / 4) + lane]);
                    s.x += v.x; s.y += v.y; s.z += v.z; s.w += v.w;
                }
            }
        }
        *(half2*)(row + 2 * D + lane * 4)     = __floats2half2_rn(s.x * inv, s.y * inv);
        *(half2*)(row + 2 * D + lane * 4 + 2) = __floats2half2_rn(s.z * inv, s.w * inv);
    }
}

// ---------------------------------------------------------------------------
__device__ __forceinline__ void cp16(void* smem, const void* gmem) {
    uint32_t s = (uint32_t)__cvta_generic_to_shared(smem);
    asm volatile("cp.async.cg.shared.global [%0], [%1], 16;" :: "r"(s), "l"(gmem));
}
__device__ __forceinline__ void mma_f16(float* a4, uint32_t a0, uint32_t a1,
                                        uint32_t a2, uint32_t a3,
                                        uint32_t b0, uint32_t b1) {
    asm volatile(
        "mma.sync.aligned.m16n8k16.row.col.f32.f16.f16.f32 "
        "{%0,%1,%2,%3}, {%4,%5,%6,%7}, {%8,%9}, {%0,%1,%2,%3};"
        : "+f"(a4[0]), "+f"(a4[1]), "+f"(a4[2]), "+f"(a4[3])
        : "r"(a0), "r"(a1), "r"(a2), "r"(a3), "r"(b0), "r"(b1));
}

// ---------------------------------------------------------------------------
// Fused MLP (fp16, BK=32, 256 threads): one CTA per 32 node-rows (= 16 pairs).
// Phase 1 (12 iters): warps 1x8, warp tile 32x32 (MF=2,NF=4) -> sN[32,256]
//   (each B fragment loaded by exactly ONE warp)
// Phase 2 (16 iters): warps 1x8, warp tile 16x32 (NF=4) -> out[16,256]
// ---------------------------------------------------------------------------
constexpr int BKH    = 32;                 // k per pipeline tile (2 x k16 mma)
constexpr int STAGES = 3;
constexpr int BM     = 32;
constexpr int SAS2   = 40;                 // A-tile halfs/row (32 data + 8 pad)
constexpr int SN2    = 260;                // sN halfs per row
constexpr int A_SZH  = BM * SAS2;          // 1280 halfs / stage
constexpr int B_SZH  = BKH * H;            // 8192 halfs / stage
constexpr int SN_H   = BM * SN2;           // 8320 halfs
constexpr int FUSED_SMEM =
    (SN_H + STAGES * A_SZH + STAGES * B_SZH) * 2;    // 73472 B

__global__ void __launch_bounds__(256, 2)
fused_mlp(const __half* __restrict__ A1full, const __half* __restrict__ W1p,
          const float* __restrict__ b1g, const __half* __restrict__ Wrp,
          const float* __restrict__ br, float* __restrict__ out) {
    constexpr int THREADS = 256;

    extern __shared__ __align__(16) __half smh[];
    __half* sN  = smh;                       // [32][SN2]
    __half* sAb = smh + SN_H;                // STAGES * A_SZH
    __half* sBb = sAb + STAGES * A_SZH;      // STAGES * B_SZH

    const int tid  = threadIdx.x;
    const int wid  = tid >> 5;
    const int lane = tid & 31;
    const int grp  = lane >> 2;
    const int tg   = lane & 3;
    const int by   = blockIdx.x;

    const __half* Ag = A1full + (size_t)by * BM * K1;

    auto issueA = [&](int t, int stg) {
        // 32 rows * 4 chunks(16B = 8 halfs) = 128; threads 0..127
        if (tid < 128) {
            __half* sA = sAb + stg * A_SZH;
            int row = tid >> 2;
            int c4  = tid & 3;
            cp16(sA + row * SAS2 + c4 * 8,
                 Ag + (size_t)row * K1 + t * BKH + c4 * 8);
        }
    };
    auto issueB = [&](const __half* Wsrc, int t, int stg) {
        __half* sB = sBb + stg * B_SZH;
        const __half* src = Wsrc + (size_t)t * B_SZH;
        #pragma unroll
        for (int l = 0; l < 4; l++) {        // 8192 halfs / (256 thr * 8) = 4
            int o = (tid + l * THREADS) * 8;
            cp16(sB + o, src + o);
        }
    };

    // =========================== PHASE 1 ===================================
    // warps 1x8: wn = wid; warp tile 32x32 (MF=2, NF=4); B loaded once/CTA
    {
        const int wn = wid;

        float acc[2][4][4];
        #pragma unroll
        for (int i = 0; i < 2; i++)
            #pragma unroll
            for (int j = 0; j < 4; j++)
                #pragma unroll
                for (int c = 0; c < 4; c++) acc[i][j][c] = 0.f;

        const int nt1 = K1 / BKH;   // 12
        #pragma unroll
        for (int s = 0; s < STAGES - 1; s++) {
            issueA(s, s); issueB(W1p, s, s);
            asm volatile("cp.async.commit_group;");
        }

        for (int t = 0; t < nt1; t++) {
            asm volatile("cp.async.wait_group %0;" :: "n"(STAGES - 2));
            __syncthreads();
            const int nt = t + STAGES - 1;
            if (nt < nt1) { issueA(nt, nt % STAGES); issueB(W1p, nt, nt % STAGES); }
            asm volatile("cp.async.commit_group;");

            const uint32_t* sAw = (const uint32_t*)(sAb + (t % STAGES) * A_SZH);
            const uint2*    sBq = (const uint2*)(sBb + (t % STAGES) * B_SZH);

            #pragma unroll
            for (int ks = 0; ks < 2; ks++) {
                uint32_t af[2][4];
                #pragma unroll
                for (int i = 0; i < 2; i++) {
                    const int rb = i * 16 + grp;
                    af[i][0] = sAw[(rb + 0) * (SAS2 / 2) + ks * 8 + tg];
                    af[i][1] = sAw[(rb + 8) * (SAS2 / 2) + ks * 8 + tg];
                    af[i][2] = sAw[(rb + 0) * (SAS2 / 2) + ks * 8 + 4 + tg];
                    af[i][3] = sAw[(rb + 8) * (SAS2 / 2) + ks * 8 + 4 + tg];
                }
                #pragma unroll
                for (int jl = 0; jl < 4; jl++) {
                    const int j = wn * 4 + jl;
                    uint2 b = sBq[ks * 1024 + j * 32 + lane];
                    #pragma unroll
                    for (int i = 0; i < 2; i++)
                        mma_f16(acc[i][jl], af[i][0], af[i][1], af[i][2], af[i][3],
                                b.x, b.y);
                }
            }
        }

        asm volatile("cp.async.wait_group 0;");

        // epilogue 1: bias + relu + fp16 -> sN
        half2* sNh2 = (half2*)sN;
        #pragma unroll
        for (int i = 0; i < 2; i++) {
            const int rb = i * 16 + grp;
            #pragma unroll
            for (int jl = 0; jl < 4; jl++) {
                const int c = wn * 32 + jl * 8 + tg * 2;
                const float b0 = b1g[c], b1v = b1g[c + 1];
                sNh2[((rb + 0) * SN2 + c) >> 1] =
                    __floats2half2_rn(fmaxf(acc[i][jl][0] + b0, 0.f),
                                      fmaxf(acc[i][jl][1] + b1v, 0.f));
                sNh2[((rb + 8) * SN2 + c) >> 1] =
                    __floats2half2_rn(fmaxf(acc[i][jl][2] + b0, 0.f),
                                      fmaxf(acc[i][jl][3] + b1v, 0.f));
            }
        }
        __syncthreads();
    }

    // =========================== PHASE 2 ===================================
    // 16 pairs x 256; warps 1x8 (wn2 = wid); warp tile 16x32 (NF=4)
    // A(p,k) = sN[(2p + (k>=256)) * SN2 + (k&255)]
    {
        const int wn2 = wid;
        const uint32_t* sNw = (const uint32_t*)sN;

        float acc[4][4];
        #pragma unroll
        for (int j = 0; j < 4; j++)
            #pragma unroll
            for (int c = 0; c < 4; c++) acc[j][c] = 0.f;

        const int nt2 = K2 / BKH;   // 16
        #pragma unroll
        for (int s = 0; s < STAGES - 1; s++) {
            issueB(Wrp, s, s);
            asm volatile("cp.async.commit_group;");
        }

        for (int t = 0; t < nt2; t++) {
            asm volatile("cp.async.wait_group %0;" :: "n"(STAGES - 2));
            __syncthreads();
            const int nt = t + STAGES - 1;
            if (nt < nt2) issueB(Wrp, nt, nt % STAGES);
            asm volatile("cp.async.commit_group;");

            const uint2* sBq = (const uint2*)(sBb + (t % STAGES) * B_SZH);

            #pragma unroll
            for (int ks = 0; ks < 2; ks++) {
                const int k   = t * BKH + ks * 16;
                const int h   = (k >= 256) ? 1 : 0;
                const int kk2 = (k & 255) >> 1;

                const uint32_t a0 = sNw[(2 * (grp + 0) + h) * (SN2 / 2) + kk2 + tg];
                const uint32_t a1 = sNw[(2 * (grp + 8) + h) * (SN2 / 2) + kk2 + tg];
                const uint32_t a2 = sNw[(2 * (grp + 0) + h) * (SN2 / 2) + kk2 + 4 + tg];
                const uint32_t a3 = sNw[(2 * (grp + 8) + h) * (SN2 / 2) + kk2 + 4 + tg];
                #pragma unroll
                for (int jl = 0; jl < 4; jl++) {
                    const int j = wn2 * 4 + jl;
                    uint2 b = sBq[ks * 1024 + j * 32 + lane];
                    mma_f16(acc[jl], a0, a1, a2, a3, b.x, b.y);
                }
            }
        }

        // epilogue 2: bias + relu -> gmem (fp32)
        const int prow = by * 16 + grp;
        #pragma unroll
        for (int jl = 0; jl < 4; jl++) {
            const int c = wn2 * 32 + jl * 8 + tg * 2;
            const float b0 = br[c], b1v = br[c + 1];
            float2 v0, v1;
            v0.x = fmaxf(acc[jl][0] + b0, 0.f);
            v0.y = fmaxf(acc[jl][1] + b1v, 0.f);
            v1.x = fmaxf(acc[jl][2] + b0, 0.f);
            v1.y = fmaxf(acc[jl][3] + b1v, 0.f);
            *(float2*)(out + (size_t)(prow + 0) * H + c) = v0;
            *(float2*)(out + (size_t)(prow + 8) * H + c) = v1;
        }
    }
}

// ---------------------------------------------------------------------------
extern "C" void kernel_launch(void* const* d_in, const int* in_sizes, int n_in,
                              void* d_out, int out_size) {
    const float* E    = (const float*)d_in[0];
    const float* R    = (const float*)d_in[1];
    const float* Wt   = (const float*)d_in[2];
    const float* bt   = (const float*)d_in[3];
    const float* Wn   = (const float*)d_in[4];
    const float* bn   = (const float*)d_in[5];
    const float* Wr   = (const float*)d_in[6];
    const float* br   = (const float*)d_in[7];
    const int*   ents = (const int*)d_in[8];
    const int*   nent = (const int*)d_in[9];
    const int*   nrel = (const int*)d_in[10];
    const int*   offs = (const int*)d_in[11];
    float* out = (float*)d_out;

    __half *A1, *W1p, *Wrp;
    float  *b1;
    cudaGetSymbolAddress((void**)&A1,  g_A1);
    cudaGetSymbolAddress((void**)&W1p, g_W1p);
    cudaGetSymbolAddress((void**)&Wrp, g_Wrp);
    cudaGetSymbolAddress((void**)&b1,  g_b1);

    cudaFuncSetAttribute(fused_mlp,
                         cudaFuncAttributeMaxDynamicSharedMemorySize, FUSED_SMEM);

    // 1) gather + segment mean (+ fused fp16 weight pack), MONOLITHIC
    gather_mean<<<NODES / 4, 256>>>(E, R, ents, nent, nrel, offs,
                                    Wt, Wn, Wr, bt, bn);

    // 2+3) fused node-MLP + pair-MLP (fp16, BK=32): 256 CTAs x 256 threads
    fused_mlp<<<NODES / BM, 256, FUSED_SMEM>>>(A1, W1p, b1, Wrp, br, out);
}